// round 2
// baseline (speedup 1.0000x reference)
#include <cuda_runtime.h>
#include <cstddef>

#define KB 8

// Scratch (allocation-free rule: static __device__ arrays)
__device__ float g_dots[65536 * 16];
__device__ float g_wv[(size_t)65536 * 1024];

// ---------------------------------------------------------------------------
// Kernel 1: dots[b,h] = (x_b @ Wq[:,h*64:+64]) . (y_b @ Wk[:,h*64:+64]) / 64
// Block: 128 rows x 1 head (64 cols). Q/K tiles live in registers only.
// ---------------------------------------------------------------------------
__global__ __launch_bounds__(256) void k_dots(
    const float* __restrict__ x, const float* __restrict__ y,
    const float* __restrict__ Wq, const float* __restrict__ Wkv,
    float* __restrict__ dots)
{
    const int h  = blockIdx.x;          // 0..15
    const int r0 = blockIdx.y * 128;
    const int c0 = h * 64;

    __shared__ float Xs[2][KB][128];
    __shared__ float Ys[2][KB][128];
    __shared__ float Qs[2][KB][64];
    __shared__ float Ks[2][KB][64];

    const int tid  = threadIdx.x;
    const int lrow = tid >> 1;          // 0..127  (x/y loader row)
    const int lk   = (tid & 1) * 4;     // 0 or 4  (x/y loader k offset)
    const bool isQ = tid < 128;         // weight loader split
    const int wt   = tid & 127;
    const int wkr  = wt >> 4;           // 0..7
    const int wn   = (wt & 15) * 4;     // 0..60
    const int row_t = tid >> 4;         // 0..15 -> 8 rows each
    const int col_t = tid & 15;         // 0..15 -> 4 cols each

    float accq[8][4], acck[8][4];
#pragma unroll
    for (int i = 0; i < 8; i++)
#pragma unroll
        for (int j = 0; j < 4; j++) { accq[i][j] = 0.f; acck[i][j] = 0.f; }

    const float* xp = x + (size_t)(r0 + lrow) * 1024 + lk;
    const float* yp = y + (size_t)(r0 + lrow) * 1024 + lk;

    // prologue: load k-slab 0 into buffer 0
    {
        float4 xv = *(const float4*)xp;
        float4 yv = *(const float4*)yp;
        Xs[0][lk+0][lrow] = xv.x; Xs[0][lk+1][lrow] = xv.y;
        Xs[0][lk+2][lrow] = xv.z; Xs[0][lk+3][lrow] = xv.w;
        Ys[0][lk+0][lrow] = yv.x; Ys[0][lk+1][lrow] = yv.y;
        Ys[0][lk+2][lrow] = yv.z; Ys[0][lk+3][lrow] = yv.w;
        if (isQ) {
            float4 wv = *(const float4*)(Wq + (size_t)wkr * 1024 + c0 + wn);
            *(float4*)&Qs[0][wkr][wn] = wv;
        } else {
            float4 wv = *(const float4*)(Wkv + (size_t)wkr * 2048 + c0 + wn);
            *(float4*)&Ks[0][wkr][wn] = wv;
        }
    }
    __syncthreads();

    int buf = 0;
    for (int kk = KB; kk <= 1024; kk += KB) {
        if (kk < 1024) {
            const int nb = buf ^ 1;
            float4 xv = *(const float4*)(xp + kk);
            float4 yv = *(const float4*)(yp + kk);
            Xs[nb][lk+0][lrow] = xv.x; Xs[nb][lk+1][lrow] = xv.y;
            Xs[nb][lk+2][lrow] = xv.z; Xs[nb][lk+3][lrow] = xv.w;
            Ys[nb][lk+0][lrow] = yv.x; Ys[nb][lk+1][lrow] = yv.y;
            Ys[nb][lk+2][lrow] = yv.z; Ys[nb][lk+3][lrow] = yv.w;
            if (isQ) {
                float4 wv = *(const float4*)(Wq + (size_t)(kk + wkr) * 1024 + c0 + wn);
                *(float4*)&Qs[nb][wkr][wn] = wv;
            } else {
                float4 wv = *(const float4*)(Wkv + (size_t)(kk + wkr) * 2048 + c0 + wn);
                *(float4*)&Ks[nb][wkr][wn] = wv;
            }
        }
#pragma unroll
        for (int k = 0; k < KB; k++) {
            float aq[8], ay[8], bq[4], bk[4];
#pragma unroll
            for (int i = 0; i < 8; i++) {
                aq[i] = Xs[buf][k][row_t * 8 + i];
                ay[i] = Ys[buf][k][row_t * 8 + i];
            }
#pragma unroll
            for (int j = 0; j < 4; j++) {
                bq[j] = Qs[buf][k][col_t * 4 + j];
                bk[j] = Ks[buf][k][col_t * 4 + j];
            }
#pragma unroll
            for (int i = 0; i < 8; i++)
#pragma unroll
                for (int j = 0; j < 4; j++) {
                    accq[i][j] += aq[i] * bq[j];
                    acck[i][j] += ay[i] * bk[j];
                }
        }
        __syncthreads();
        buf ^= 1;
    }

    // per-row q.k partial over this thread's 4 cols, reduce over 16 col_t lanes
    const float s2 = 1.0f / 64.0f;   // scale^2 (double-scale in reference)
#pragma unroll
    for (int i = 0; i < 8; i++) {
        float p = accq[i][0] * acck[i][0] + accq[i][1] * acck[i][1]
                + accq[i][2] * acck[i][2] + accq[i][3] * acck[i][3];
        p += __shfl_xor_sync(0xffffffffu, p, 1);
        p += __shfl_xor_sync(0xffffffffu, p, 2);
        p += __shfl_xor_sync(0xffffffffu, p, 4);
        p += __shfl_xor_sync(0xffffffffu, p, 8);
        if (col_t == 0)
            dots[(size_t)(r0 + row_t * 8 + i) * 16 + h] = p * s2;
    }
}

// ---------------------------------------------------------------------------
// Kernel 2: softmax over the 16 heads, in place. One row per thread.
// ---------------------------------------------------------------------------
__global__ void k_softmax(float* __restrict__ dots, int B)
{
    int r = blockIdx.x * 256 + threadIdx.x;
    if (r >= B) return;
    float4* p = (float4*)(dots + (size_t)r * 16);
    float4 a0 = p[0], a1 = p[1], a2 = p[2], a3 = p[3];
    float v[16] = { a0.x,a0.y,a0.z,a0.w, a1.x,a1.y,a1.z,a1.w,
                    a2.x,a2.y,a2.z,a2.w, a3.x,a3.y,a3.z,a3.w };
    float m = v[0];
#pragma unroll
    for (int i = 1; i < 16; i++) m = fmaxf(m, v[i]);
    float s = 0.f;
#pragma unroll
    for (int i = 0; i < 16; i++) { v[i] = __expf(v[i] - m); s += v[i]; }
    float inv = 1.0f / s;
#pragma unroll
    for (int i = 0; i < 16; i++) v[i] *= inv;
    p[0] = make_float4(v[0], v[1], v[2], v[3]);
    p[1] = make_float4(v[4], v[5], v[6], v[7]);
    p[2] = make_float4(v[8], v[9], v[10], v[11]);
    p[3] = make_float4(v[12], v[13], v[14], v[15]);
}

// ---------------------------------------------------------------------------
// Kernels 3/4: 128x128 fp32 GEMM, double-buffered, 8x8 per thread.
// MODE 0: C = (A @ Bm) * attn[row, col/64]   (aux = attn, strided Bm = Wv)
// MODE 1: C = (A @ Bm) + bias[col]           (aux = bproj)
// ---------------------------------------------------------------------------
template <int MODE>
__global__ __launch_bounds__(256) void k_gemm(
    const float* __restrict__ A, const float* __restrict__ Bm, int ldb,
    const float* __restrict__ aux, float* __restrict__ C)
{
    const int c0 = blockIdx.x * 128;
    const int r0 = blockIdx.y * 128;

    __shared__ float As[2][KB][128];
    __shared__ float Bs[2][KB][128];

    const int tid  = threadIdx.x;
    const int lrow = tid >> 1;            // A loader
    const int lk   = (tid & 1) * 4;
    const int bkr  = tid >> 5;            // B loader: 8 rows x 32 thr x float4
    const int bn4  = (tid & 31) * 4;
    const int row_t = tid >> 4;
    const int col_t = tid & 15;

    float acc[8][8];
#pragma unroll
    for (int i = 0; i < 8; i++)
#pragma unroll
        for (int j = 0; j < 8; j++) acc[i][j] = 0.f;

    const float* Ap = A + (size_t)(r0 + lrow) * 1024 + lk;
    const float* Bp = Bm + (size_t)bkr * ldb + c0 + bn4;

    {
        float4 av = *(const float4*)Ap;
        As[0][lk+0][lrow] = av.x; As[0][lk+1][lrow] = av.y;
        As[0][lk+2][lrow] = av.z; As[0][lk+3][lrow] = av.w;
        float4 bv = *(const float4*)Bp;
        *(float4*)&Bs[0][bkr][bn4] = bv;
    }
    __syncthreads();

    int buf = 0;
    for (int kk = KB; kk <= 1024; kk += KB) {
        if (kk < 1024) {
            const int nb = buf ^ 1;
            float4 av = *(const float4*)(Ap + kk);
            As[nb][lk+0][lrow] = av.x; As[nb][lk+1][lrow] = av.y;
            As[nb][lk+2][lrow] = av.z; As[nb][lk+3][lrow] = av.w;
            float4 bv = *(const float4*)(Bp + (size_t)kk * ldb);
            *(float4*)&Bs[nb][bkr][bn4] = bv;
        }
#pragma unroll
        for (int k = 0; k < KB; k++) {
            float a[8], b[8];
#pragma unroll
            for (int i = 0; i < 8; i++) a[i] = As[buf][k][row_t * 8 + i];
#pragma unroll
            for (int j = 0; j < 8; j++) b[j] = Bs[buf][k][col_t * 8 + j];
#pragma unroll
            for (int i = 0; i < 8; i++)
#pragma unroll
                for (int j = 0; j < 8; j++) acc[i][j] += a[i] * b[j];
        }
        __syncthreads();
        buf ^= 1;
    }

    const int ccol = c0 + col_t * 8;      // 8-aligned: never crosses a head
    if (MODE == 0) {
        const int h = ccol >> 6;
#pragma unroll
        for (int i = 0; i < 8; i++) {
            const int row = r0 + row_t * 8 + i;
            const float s = aux[(size_t)row * 16 + h];
            float4 o0 = make_float4(acc[i][0]*s, acc[i][1]*s, acc[i][2]*s, acc[i][3]*s);
            float4 o1 = make_float4(acc[i][4]*s, acc[i][5]*s, acc[i][6]*s, acc[i][7]*s);
            float* cp = C + (size_t)row * 1024 + ccol;
            *(float4*)cp = o0;
            *(float4*)(cp + 4) = o1;
        }
    } else {
        float bb[8];
#pragma unroll
        for (int j = 0; j < 8; j++) bb[j] = aux[ccol + j];
#pragma unroll
        for (int i = 0; i < 8; i++) {
            const int row = r0 + row_t * 8 + i;
            float4 o0 = make_float4(acc[i][0]+bb[0], acc[i][1]+bb[1], acc[i][2]+bb[2], acc[i][3]+bb[3]);
            float4 o1 = make_float4(acc[i][4]+bb[4], acc[i][5]+bb[5], acc[i][6]+bb[6], acc[i][7]+bb[7]);
            float* cp = C + (size_t)row * 1024 + ccol;
            *(float4*)cp = o0;
            *(float4*)(cp + 4) = o1;
        }
    }
}

// ---------------------------------------------------------------------------
// Launch: dots -> softmax -> (v GEMM * attn) -> proj GEMM + bias
// Inputs (metadata order): x, y, mask, Wq, Wkv, Wproj, bproj
// ---------------------------------------------------------------------------
extern "C" void kernel_launch(void* const* d_in, const int* in_sizes, int n_in,
                              void* d_out, int out_size)
{
    const float* x     = (const float*)d_in[0];
    const float* y     = (const float*)d_in[1];
    // d_in[2] = mask (unused by the module)
    const float* Wq    = (const float*)d_in[3];
    const float* Wkv   = (const float*)d_in[4];
    const float* Wproj = (const float*)d_in[5];
    const float* bproj = (const float*)d_in[6];
    float* out = (float*)d_out;

    const int B = in_sizes[0] / 1024;

    float *dots, *wv;
    cudaGetSymbolAddress((void**)&dots, g_dots);
    cudaGetSymbolAddress((void**)&wv,   g_wv);

    dim3 gDots(16, B / 128);
    k_dots<<<gDots, 256>>>(x, y, Wq, Wkv, dots);

    k_softmax<<<(B + 255) / 256, 256>>>(dots, B);

    dim3 gGemm(1024 / 128, B / 128);
    k_gemm<0><<<gGemm, 256>>>(y, Wkv + 1024, 2048, dots, wv);   // v GEMM (Wv cols) * attn
    k_gemm<1><<<gGemm, 256>>>(wv, Wproj, 1024, bproj, out);     // proj + bias
}

// round 6
// speedup vs baseline: 2.3076x; 2.3076x over previous
#include <cuda_runtime.h>
#include <cuda_bf16.h>
#include <cstdint>
#include <cstddef>

typedef unsigned short ushort_t;

// ---------------------------------------------------------------------------
// Scratch (static __device__ arrays; allocation-free rule)
// ---------------------------------------------------------------------------
__device__ float    g_q   [(size_t)65536 * 1024];
__device__ float    g_kv  [(size_t)65536 * 2048];
__device__ ushort_t g_xhi [(size_t)65536 * 1024];
__device__ ushort_t g_xlo [(size_t)65536 * 1024];
__device__ ushort_t g_yhi [(size_t)65536 * 1024];
__device__ ushort_t g_ylo [(size_t)65536 * 1024];
__device__ ushort_t g_wvhi[(size_t)65536 * 1024];
__device__ ushort_t g_wvlo[(size_t)65536 * 1024];
__device__ ushort_t g_whi [4u * 1024u * 1024u];   // W^T bf16 hi, [mat][n][k]
__device__ ushort_t g_wlo [4u * 1024u * 1024u];   // W^T bf16 lo

// ---------------------------------------------------------------------------
// Portable (sm_80-era) PTX helpers: cp.async, ldmatrix, mma.sync — all valid
// on base sm_100 (tcgen05/TMA are sm_100a-only and rejected by this bench).
// ---------------------------------------------------------------------------
__device__ __forceinline__ uint32_t smem_to_u32(const void* p) {
    uint32_t a;
    asm("{ .reg .u64 t; cvta.to.shared.u64 t, %1; cvt.u32.u64 %0, t; }" : "=r"(a) : "l"(p));
    return a;
}
__device__ __forceinline__ void cp_async16(uint32_t dst, const void* src) {
    asm volatile("cp.async.cg.shared.global [%0], [%1], 16;" :: "r"(dst), "l"(src));
}
#define CP_COMMIT()     asm volatile("cp.async.commit_group;" ::: "memory")
#define CP_WAIT(n)      asm volatile("cp.async.wait_group %0;" :: "n"(n) : "memory")

__device__ __forceinline__ void ldsm4(uint32_t* r, uint32_t addr) {
    asm volatile("ldmatrix.sync.aligned.m8n8.x4.shared.b16 {%0,%1,%2,%3}, [%4];"
                 : "=r"(r[0]), "=r"(r[1]), "=r"(r[2]), "=r"(r[3]) : "r"(addr));
}
__device__ __forceinline__ void mma16816(float* c, const uint32_t* a, const uint32_t* b) {
    asm volatile("mma.sync.aligned.m16n8k16.row.col.f32.bf16.bf16.f32 "
                 "{%0,%1,%2,%3}, {%4,%5,%6,%7}, {%8,%9}, {%0,%1,%2,%3};"
                 : "+f"(c[0]), "+f"(c[1]), "+f"(c[2]), "+f"(c[3])
                 : "r"(a[0]), "r"(a[1]), "r"(a[2]), "r"(a[3]), "r"(b[0]), "r"(b[1]));
}
__device__ __forceinline__ uint32_t bf16x2_rn(float hi_val, float lo_val) {
    uint32_t r;
    asm("cvt.rn.bf16x2.f32 %0, %1, %2;" : "=r"(r) : "f"(hi_val), "f"(lo_val));
    return r;
}

// smem swizzle: XOR 16B-unit index (bits 4-6) with row%8 (bits 7-9). Rows = 128B.
#define SW128(off) ((off) ^ (((off) >> 3) & 0x70))

// SMEM: A region [buf][half][128][64]bf16 (16KB each), B region likewise at +64KB.
static constexpr int SMEM_BYTES = 131072;

// ---------------------------------------------------------------------------
// Activation split: hi = bf16_rn(a); lo = bf16_rn(a - hi). float4 vectorized.
// ---------------------------------------------------------------------------
__global__ void k_split(const float4* __restrict__ in, uint2* __restrict__ hi,
                        uint2* __restrict__ lo, int n4)
{
    int i = blockIdx.x * 256 + threadIdx.x;
    if (i >= n4) return;
    const float4 v = in[i];
    uint2 H, L;
    H.x = bf16x2_rn(v.y, v.x);
    H.y = bf16x2_rn(v.w, v.z);
    const float hx = __uint_as_float(H.x << 16);
    const float hy = __uint_as_float(H.x & 0xFFFF0000u);
    const float hz = __uint_as_float(H.y << 16);
    const float hw = __uint_as_float(H.y & 0xFFFF0000u);
    L.x = bf16x2_rn(v.y - hy, v.x - hx);
    L.y = bf16x2_rn(v.w - hw, v.z - hz);
    hi[i] = H;
    lo[i] = L;
}

// ---------------------------------------------------------------------------
// Weight prep: Wt_{hi,lo}[mat][n][k] = rn-split of W[k][n] (transposed)
// ---------------------------------------------------------------------------
__global__ void k_prep_w(const float* __restrict__ Wq, const float* __restrict__ Wkv,
                         const float* __restrict__ Wproj)
{
    __shared__ float t[32][33];
    const int m = blockIdx.z;
    const float* src; int ld; int coff = 0;
    if (m == 0)      { src = Wq;    ld = 1024; }
    else if (m == 1) { src = Wkv;   ld = 2048; }
    else if (m == 2) { src = Wkv;   ld = 2048; coff = 1024; }
    else             { src = Wproj; ld = 1024; }
    const int n0 = blockIdx.x * 32, k0 = blockIdx.y * 32;
    const int tx = threadIdx.x, ty = threadIdx.y;
#pragma unroll
    for (int j = 0; j < 4; j++)
        t[ty + j * 8][tx] = src[(size_t)(k0 + ty + j * 8) * ld + coff + n0 + tx];
    __syncthreads();
    const size_t base = (size_t)m * 1048576u;
#pragma unroll
    for (int j = 0; j < 4; j++) {
        const int n = n0 + ty + j * 8;
        const int k = k0 + tx;
        const float a = t[tx][ty + j * 8];
        const uint32_t hb = bf16x2_rn(0.f, a);          // low half = bf16_rn(a)
        const float hf = __uint_as_float(hb << 16);
        const uint32_t lb = bf16x2_rn(0.f, a - hf);
        g_whi[base + (size_t)n * 1024 + k] = (ushort_t)(hb & 0xFFFFu);
        g_wlo[base + (size_t)n * 1024 + k] = (ushort_t)(lb & 0xFFFFu);
    }
}

// ---------------------------------------------------------------------------
// Core 128x128 GEMM tile on mma.sync bf16 with 3-pass split accumulation.
// A: [row][1024] hi/lo, B: [n][1024] hi/lo (pre-offset to the 128-col slice).
// ---------------------------------------------------------------------------
__device__ __forceinline__ void stage_chunk(
    uint32_t sA, uint32_t sB, int buf, int kk,
    const ushort_t* __restrict__ Ah, const ushort_t* __restrict__ Al,
    const ushort_t* __restrict__ Bh, const ushort_t* __restrict__ Bl,
    size_t arow0, int tid)
{
    const int r  = tid >> 1;
    const int ub = (tid & 1) * 4;
    const uint32_t boff = (uint32_t)buf * 32768u;
    const size_t aoff = (arow0 + r) * 1024 + kk + ub * 8;
    const size_t woff = (size_t)r * 1024 + kk + ub * 8;
#pragma unroll
    for (int u = 0; u < 4; u++) {
        const uint32_t dsw = SW128((uint32_t)(r * 128 + (ub + u) * 16));
        cp_async16(sA + boff +          dsw, Ah + aoff + u * 8);
        cp_async16(sA + boff + 16384u + dsw, Al + aoff + u * 8);
        cp_async16(sB + boff +          dsw, Bh + woff + u * 8);
        cp_async16(sB + boff + 16384u + dsw, Bl + woff + u * 8);
    }
}

__device__ __forceinline__ void gemm_tile(
    const ushort_t* __restrict__ Ah, const ushort_t* __restrict__ Al, size_t arow0,
    const ushort_t* __restrict__ Bh, const ushort_t* __restrict__ Bl,
    float* __restrict__ C, size_t ldc, int ccol, const float* __restrict__ bias)
{
    extern __shared__ char smem[];
    const uint32_t sA = smem_to_u32(smem);
    const uint32_t sB = sA + 65536u;
    const int tid = threadIdx.x, lane = tid & 31, wid = tid >> 5;
    const int wm = (wid & 1) * 64;        // 2 warp rows x 64
    const int wn = (wid >> 1) * 32;       // 4 warp cols x 32

    float acc[4][4][4];
#pragma unroll
    for (int i = 0; i < 4; i++)
#pragma unroll
        for (int j = 0; j < 4; j++)
#pragma unroll
            for (int k = 0; k < 4; k++) acc[i][j][k] = 0.f;

    stage_chunk(sA, sB, 0, 0, Ah, Al, Bh, Bl, arow0, tid);
    CP_COMMIT();

    for (int c = 0; c < 16; c++) {
        if (c < 15) {
            stage_chunk(sA, sB, (c + 1) & 1, (c + 1) * 64, Ah, Al, Bh, Bl, arow0, tid);
            CP_COMMIT();
            CP_WAIT(1);
        } else {
            CP_WAIT(0);
        }
        __syncthreads();
        const uint32_t aB = sA + ((uint32_t)(c & 1)) * 32768u;
        const uint32_t bB = sB + ((uint32_t)(c & 1)) * 32768u;
#pragma unroll
        for (int s = 0; s < 4; s++) {
            uint32_t a[2][4][4];
#pragma unroll
            for (int half = 0; half < 2; half++)
#pragma unroll
                for (int im = 0; im < 4; im++) {
                    const uint32_t row = wm + im * 16 + (lane & 15);
                    const uint32_t addr = aB + half * 16384u +
                        SW128(row * 128 + s * 32 + ((lane >> 4) * 16));
                    ldsm4(a[half][im], addr);
                }
            uint32_t b[2][4][2];
#pragma unroll
            for (int half = 0; half < 2; half++)
#pragma unroll
                for (int p = 0; p < 2; p++) {
                    const uint32_t t4 = lane >> 3;
                    const uint32_t n = wn + p * 16 + ((t4 >> 1) << 3) + (lane & 7);
                    const uint32_t addr = bB + half * 16384u +
                        SW128(n * 128 + s * 32 + ((t4 & 1) * 16));
                    uint32_t r4[4];
                    ldsm4(r4, addr);
                    b[half][p * 2 + 0][0] = r4[0]; b[half][p * 2 + 0][1] = r4[1];
                    b[half][p * 2 + 1][0] = r4[2]; b[half][p * 2 + 1][1] = r4[3];
                }
            // pass-major ordering: 16 independent acc tiles between reuses
#pragma unroll
            for (int im = 0; im < 4; im++)
#pragma unroll
                for (int jn = 0; jn < 4; jn++)
                    mma16816(acc[im][jn], a[0][im], b[0][jn]);   // hi*hi
#pragma unroll
            for (int im = 0; im < 4; im++)
#pragma unroll
                for (int jn = 0; jn < 4; jn++)
                    mma16816(acc[im][jn], a[0][im], b[1][jn]);   // hi*lo
#pragma unroll
            for (int im = 0; im < 4; im++)
#pragma unroll
                for (int jn = 0; jn < 4; jn++)
                    mma16816(acc[im][jn], a[1][im], b[0][jn]);   // lo*hi
        }
        __syncthreads();
    }

    // Epilogue: direct fp32 stores (32B sectors per quarter-warp)
#pragma unroll
    for (int im = 0; im < 4; im++) {
        const size_t m0 = arow0 + wm + im * 16 + (lane >> 2);
#pragma unroll
        for (int jn = 0; jn < 4; jn++) {
            const int col = ccol + wn + jn * 8 + (lane & 3) * 2;
            float2 v0 = make_float2(acc[im][jn][0], acc[im][jn][1]);
            float2 v1 = make_float2(acc[im][jn][2], acc[im][jn][3]);
            if (bias) {
                const float2 bb = *(const float2*)(bias + col);
                v0.x += bb.x; v0.y += bb.y; v1.x += bb.x; v1.y += bb.y;
            }
            *(float2*)(C + m0 * ldc + col) = v0;
            *(float2*)(C + (m0 + 8) * ldc + col) = v1;
        }
    }
}

// ---------------------------------------------------------------------------
// GEMM kernels
// ---------------------------------------------------------------------------
__global__ __launch_bounds__(256, 1) void k_gemm_qkv()
{
    const int ct = blockIdx.x;            // 0-7: q, 8-15: k, 16-23: v
    const size_t rt = blockIdx.y;
    const ushort_t* Ah = (ct < 8) ? g_xhi : g_yhi;
    const ushort_t* Al = (ct < 8) ? g_xlo : g_ylo;
    const int mat = (ct < 8) ? 0 : ((ct < 16) ? 1 : 2);
    const int nc = (ct & 7) * 128;
    const ushort_t* Bh = g_whi + (size_t)mat * 1048576u + (size_t)nc * 1024;
    const ushort_t* Bl = g_wlo + (size_t)mat * 1048576u + (size_t)nc * 1024;

    float* C; size_t ldc; int ccol;
    if (ct < 8)       { C = g_q;  ldc = 1024; ccol = nc; }
    else if (ct < 16) { C = g_kv; ldc = 2048; ccol = nc; }
    else              { C = g_kv; ldc = 2048; ccol = 1024 + nc; }

    gemm_tile(Ah, Al, rt * 128, Bh, Bl, C, ldc, ccol, nullptr);
}

__global__ __launch_bounds__(256, 1) void k_gemm_proj(
    const float* __restrict__ bproj, float* __restrict__ out)
{
    const int ct = blockIdx.x;            // 0..7
    const size_t rt = blockIdx.y;
    const int nc = ct * 128;
    const ushort_t* Bh = g_whi + (size_t)3 * 1048576u + (size_t)nc * 1024;
    const ushort_t* Bl = g_wlo + (size_t)3 * 1048576u + (size_t)nc * 1024;
    gemm_tile(g_wvhi, g_wvlo, rt * 128, Bh, Bl, out, 1024, nc, bproj - nc + 0 + nc == bproj ? bproj : bproj);
}

// ---------------------------------------------------------------------------
// dots + softmax(16 heads) + attn*v -> wv hi/lo (bf16 split, ready for proj)
// 256 threads = 16 rows x 16 heads
// ---------------------------------------------------------------------------
__global__ __launch_bounds__(256) void k_attn()
{
    const int tid = threadIdx.x;
    const int h = tid & 15;
    const size_t r = (size_t)blockIdx.x * 16 + (tid >> 4);
    const float4* qp = (const float4*)(g_q  + r * 1024 + h * 64);
    const float4* kp = (const float4*)(g_kv + r * 2048 + h * 64);
    const float4* vp = (const float4*)(g_kv + r * 2048 + 1024 + h * 64);

    float acc = 0.f;
#pragma unroll
    for (int j = 0; j < 16; j++) {
        const float4 a = qp[j], b = kp[j];
        acc += a.x * b.x + a.y * b.y + a.z * b.z + a.w * b.w;
    }
    const float d = acc * (1.0f / 64.0f);   // scale^2 (double-scale in reference)

    float m = d;
#pragma unroll
    for (int s = 8; s; s >>= 1) m = fmaxf(m, __shfl_xor_sync(0xffffffffu, m, s, 16));
    const float e = __expf(d - m);
    float ssum = e;
#pragma unroll
    for (int s = 8; s; s >>= 1) ssum += __shfl_xor_sync(0xffffffffu, ssum, s, 16);
    const float attn = e / ssum;

    uint2* wh = (uint2*)(g_wvhi + r * 1024 + h * 64);
    uint2* wl = (uint2*)(g_wvlo + r * 1024 + h * 64);
#pragma unroll
    for (int j = 0; j < 16; j++) {
        const float4 v = vp[j];
        const float sx = v.x * attn, sy = v.y * attn, sz = v.z * attn, sw = v.w * attn;
        uint2 H, L;
        H.x = bf16x2_rn(sy, sx);
        H.y = bf16x2_rn(sw, sz);
        const float hx = __uint_as_float(H.x << 16);
        const float hy = __uint_as_float(H.x & 0xFFFF0000u);
        const float hz = __uint_as_float(H.y << 16);
        const float hw = __uint_as_float(H.y & 0xFFFF0000u);
        L.x = bf16x2_rn(sy - hy, sx - hx);
        L.y = bf16x2_rn(sw - hw, sz - hz);
        wh[j] = H;
        wl[j] = L;
    }
}

// ---------------------------------------------------------------------------
// Launch. Inputs: x, y, mask(unused), Wq, Wkv, Wproj, bproj
// ---------------------------------------------------------------------------
extern "C" void kernel_launch(void* const* d_in, const int* in_sizes, int n_in,
                              void* d_out, int out_size)
{
    const float* x     = (const float*)d_in[0];
    const float* y     = (const float*)d_in[1];
    const float* Wq    = (const float*)d_in[3];
    const float* Wkv   = (const float*)d_in[4];
    const float* Wproj = (const float*)d_in[5];
    const float* bproj = (const float*)d_in[6];
    float* out = (float*)d_out;

    const int B = in_sizes[0] / 1024;
    const int n4 = B * 1024 / 4;

    ushort_t *xhi, *xlo, *yhi, *ylo;
    cudaGetSymbolAddress((void**)&xhi, g_xhi);
    cudaGetSymbolAddress((void**)&xlo, g_xlo);
    cudaGetSymbolAddress((void**)&yhi, g_yhi);
    cudaGetSymbolAddress((void**)&ylo, g_ylo);

    cudaFuncSetAttribute(k_gemm_qkv,  cudaFuncAttributeMaxDynamicSharedMemorySize, SMEM_BYTES);
    cudaFuncSetAttribute(k_gemm_proj, cudaFuncAttributeMaxDynamicSharedMemorySize, SMEM_BYTES);

    k_split<<<(n4 + 255) / 256, 256>>>((const float4*)x, (uint2*)xhi, (uint2*)xlo, n4);
    k_split<<<(n4 + 255) / 256, 256>>>((const float4*)y, (uint2*)yhi, (uint2*)ylo, n4);
    k_prep_w<<<dim3(32, 32, 4), dim3(32, 8)>>>(Wq, Wkv, Wproj);

    k_gemm_qkv<<<dim3(24, B / 128), 256, SMEM_BYTES>>>();
    k_attn<<<B / 16, 256>>>();
    k_gemm_proj<<<dim3(8, B / 128), 256, SMEM_BYTES>>>(bproj, out);
}

// round 7
// speedup vs baseline: 3.7305x; 1.6166x over previous
#include <cuda_runtime.h>
#include <cuda_fp16.h>
#include <cstdint>
#include <cstddef>

typedef unsigned short ushort_t;

// ---------------------------------------------------------------------------
// Scratch (static __device__ arrays; allocation-free rule)
// ---------------------------------------------------------------------------
__device__ float    g_q   [(size_t)65536 * 1024];
__device__ float    g_kv  [(size_t)65536 * 2048];
__device__ ushort_t g_xh  [(size_t)65536 * 1024];   // x as fp16
__device__ ushort_t g_yh  [(size_t)65536 * 1024];   // y as fp16
__device__ ushort_t g_wvh [(size_t)65536 * 1024];   // attn*v as fp16
__device__ ushort_t g_whi [4u * 1024u * 1024u];     // W^T fp16 hi, [mat][n][k]
__device__ ushort_t g_wlo [4u * 1024u * 1024u];     // W^T fp16 lo (residual)

// ---------------------------------------------------------------------------
// Portable (sm_80-era) PTX helpers — valid on base sm_100 target.
// ---------------------------------------------------------------------------
__device__ __forceinline__ uint32_t smem_to_u32(const void* p) {
    uint32_t a;
    asm("{ .reg .u64 t; cvta.to.shared.u64 t, %1; cvt.u32.u64 %0, t; }" : "=r"(a) : "l"(p));
    return a;
}
__device__ __forceinline__ void cp_async16(uint32_t dst, const void* src) {
    asm volatile("cp.async.cg.shared.global [%0], [%1], 16;" :: "r"(dst), "l"(src));
}
#define CP_COMMIT()     asm volatile("cp.async.commit_group;" ::: "memory")
#define CP_WAIT(n)      asm volatile("cp.async.wait_group %0;" :: "n"(n) : "memory")

__device__ __forceinline__ void ldsm4(uint32_t* r, uint32_t addr) {
    asm volatile("ldmatrix.sync.aligned.m8n8.x4.shared.b16 {%0,%1,%2,%3}, [%4];"
                 : "=r"(r[0]), "=r"(r[1]), "=r"(r[2]), "=r"(r[3]) : "r"(addr));
}
__device__ __forceinline__ void mma16816(float* c, const uint32_t* a, const uint32_t* b) {
    asm volatile("mma.sync.aligned.m16n8k16.row.col.f32.f16.f16.f32 "
                 "{%0,%1,%2,%3}, {%4,%5,%6,%7}, {%8,%9}, {%0,%1,%2,%3};"
                 : "+f"(c[0]), "+f"(c[1]), "+f"(c[2]), "+f"(c[3])
                 : "r"(a[0]), "r"(a[1]), "r"(a[2]), "r"(a[3]), "r"(b[0]), "r"(b[1]));
}
__device__ __forceinline__ uint32_t f16x2_rn(float hi_val, float lo_val) {
    uint32_t r;
    asm("cvt.rn.f16x2.f32 %0, %1, %2;" : "=r"(r) : "f"(hi_val), "f"(lo_val));
    return r;    // low 16 bits = lo_val
}

// smem swizzle: XOR 16B-unit index (bits 4-6) with row%8 (bits 7-9). Rows = 128B.
#define SW128(off) ((off) ^ (((off) >> 3) & 0x70))

// Stage = A(16KB) + Bh(16KB) + Bl(16KB) = 48KB; 2 stages = 96KB -> 2 CTAs/SM.
static constexpr uint32_t STAGE_BYTES = 49152;
static constexpr int SMEM_BYTES = 2 * 49152;

// ---------------------------------------------------------------------------
// Activation convert: fp32 -> fp16 (round-to-nearest), float4 vectorized.
// ---------------------------------------------------------------------------
__global__ void k_cvt(const float4* __restrict__ in, uint2* __restrict__ out, int n4)
{
    int i = blockIdx.x * 256 + threadIdx.x;
    if (i >= n4) return;
    const float4 v = in[i];
    uint2 H;
    H.x = f16x2_rn(v.y, v.x);
    H.y = f16x2_rn(v.w, v.z);
    out[i] = H;
}

// ---------------------------------------------------------------------------
// Weight prep: Wt_{hi,lo}[mat][n][k] = fp16 split of W[k][n] (transposed)
// ---------------------------------------------------------------------------
__global__ void k_prep_w(const float* __restrict__ Wq, const float* __restrict__ Wkv,
                         const float* __restrict__ Wproj)
{
    __shared__ float t[32][33];
    const int m = blockIdx.z;
    const float* src; int ld; int coff = 0;
    if (m == 0)      { src = Wq;    ld = 1024; }
    else if (m == 1) { src = Wkv;   ld = 2048; }
    else if (m == 2) { src = Wkv;   ld = 2048; coff = 1024; }
    else             { src = Wproj; ld = 1024; }
    const int n0 = blockIdx.x * 32, k0 = blockIdx.y * 32;
    const int tx = threadIdx.x, ty = threadIdx.y;
#pragma unroll
    for (int j = 0; j < 4; j++)
        t[ty + j * 8][tx] = src[(size_t)(k0 + ty + j * 8) * ld + coff + n0 + tx];
    __syncthreads();
    const size_t base = (size_t)m * 1048576u;
#pragma unroll
    for (int j = 0; j < 4; j++) {
        const int n = n0 + ty + j * 8;
        const int k = k0 + tx;
        const float a = t[tx][ty + j * 8];
        const __half hh = __float2half_rn(a);
        const __half hl = __float2half_rn(a - __half2float(hh));
        g_whi[base + (size_t)n * 1024 + k] = __half_as_ushort(hh);
        g_wlo[base + (size_t)n * 1024 + k] = __half_as_ushort(hl);
    }
}

// ---------------------------------------------------------------------------
// Stage one K=64 chunk: A[128x64] fp16 + Bh/Bl[128x64] fp16 via cp.async.
// ---------------------------------------------------------------------------
__device__ __forceinline__ void stage_chunk(
    uint32_t sbase, int buf, int kk,
    const ushort_t* __restrict__ Ah,
    const ushort_t* __restrict__ Bh, const ushort_t* __restrict__ Bl,
    size_t arow0, int tid)
{
    const int r  = tid >> 1;            // 0..127 (row / n index)
    const int ub = (tid & 1) * 4;       // 16B-unit offset 0 or 4
    const uint32_t so = sbase + (uint32_t)buf * STAGE_BYTES;
    const size_t aoff = (arow0 + r) * 1024 + kk + ub * 8;
    const size_t woff = (size_t)r * 1024 + kk + ub * 8;
#pragma unroll
    for (int u = 0; u < 4; u++) {
        const uint32_t dsw = SW128((uint32_t)(r * 128 + (ub + u) * 16));
        cp_async16(so +          dsw, Ah + aoff + u * 8);
        cp_async16(so + 16384u + dsw, Bh + woff + u * 8);
        cp_async16(so + 32768u + dsw, Bl + woff + u * 8);
    }
}

// ---------------------------------------------------------------------------
// Core 128x128 GEMM tile: D = A_fp16 @ (Bh + Bl)^T, 2-pass fp16 mma.sync.
// ---------------------------------------------------------------------------
__device__ __forceinline__ void gemm_tile(
    const ushort_t* __restrict__ Ah, size_t arow0,
    const ushort_t* __restrict__ Bh, const ushort_t* __restrict__ Bl,
    float* __restrict__ C, size_t ldc, int ccol, const float* __restrict__ bias)
{
    extern __shared__ char smem[];
    const uint32_t sbase = smem_to_u32(smem);
    const int tid = threadIdx.x, lane = tid & 31, wid = tid >> 5;
    const int wm = (wid & 1) * 64;        // 2 warp rows x 64
    const int wn = (wid >> 1) * 32;       // 4 warp cols x 32

    float acc[4][4][4];
#pragma unroll
    for (int i = 0; i < 4; i++)
#pragma unroll
        for (int j = 0; j < 4; j++)
#pragma unroll
            for (int k = 0; k < 4; k++) acc[i][j][k] = 0.f;

    stage_chunk(sbase, 0, 0, Ah, Bh, Bl, arow0, tid);
    CP_COMMIT();

    for (int c = 0; c < 16; c++) {
        if (c < 15) {
            stage_chunk(sbase, (c + 1) & 1, (c + 1) * 64, Ah, Bh, Bl, arow0, tid);
            CP_COMMIT();
            CP_WAIT(1);
        } else {
            CP_WAIT(0);
        }
        __syncthreads();
        const uint32_t so = sbase + ((uint32_t)(c & 1)) * STAGE_BYTES;
#pragma unroll
        for (int s = 0; s < 4; s++) {
            uint32_t a[4][4];
#pragma unroll
            for (int im = 0; im < 4; im++) {
                const uint32_t row = wm + im * 16 + (lane & 15);
                const uint32_t addr = so + SW128(row * 128 + s * 32 + ((lane >> 4) * 16));
                ldsm4(a[im], addr);
            }
#pragma unroll
            for (int half = 0; half < 2; half++) {
                const uint32_t bB = so + 16384u + (uint32_t)half * 16384u;
                uint32_t b[4][2];
#pragma unroll
                for (int p = 0; p < 2; p++) {
                    const uint32_t t4 = lane >> 3;
                    const uint32_t n = wn + p * 16 + ((t4 >> 1) << 3) + (lane & 7);
                    const uint32_t addr = bB + SW128(n * 128 + s * 32 + ((t4 & 1) * 16));
                    uint32_t r4[4];
                    ldsm4(r4, addr);
                    b[p * 2 + 0][0] = r4[0]; b[p * 2 + 0][1] = r4[1];
                    b[p * 2 + 1][0] = r4[2]; b[p * 2 + 1][1] = r4[3];
                }
#pragma unroll
                for (int im = 0; im < 4; im++)
#pragma unroll
                    for (int jn = 0; jn < 4; jn++)
                        mma16816(acc[im][jn], a[im], b[jn]);
            }
        }
        __syncthreads();
    }

    // Epilogue: direct fp32 stores
#pragma unroll
    for (int im = 0; im < 4; im++) {
        const size_t m0 = arow0 + wm + im * 16 + (lane >> 2);
#pragma unroll
        for (int jn = 0; jn < 4; jn++) {
            const int col = ccol + wn + jn * 8 + (lane & 3) * 2;
            float2 v0 = make_float2(acc[im][jn][0], acc[im][jn][1]);
            float2 v1 = make_float2(acc[im][jn][2], acc[im][jn][3]);
            if (bias) {
                const float2 bb = *(const float2*)(bias + col);
                v0.x += bb.x; v0.y += bb.y; v1.x += bb.x; v1.y += bb.y;
            }
            *(float2*)(C + m0 * ldc + col) = v0;
            *(float2*)(C + (m0 + 8) * ldc + col) = v1;
        }
    }
}

// ---------------------------------------------------------------------------
// GEMM kernels
// ---------------------------------------------------------------------------
__global__ __launch_bounds__(256, 2) void k_gemm_qkv()
{
    const int ct = blockIdx.x;            // 0-7: q, 8-15: k, 16-23: v
    const size_t rt = blockIdx.y;
    const ushort_t* Ah = (ct < 8) ? g_xh : g_yh;
    const int mat = (ct < 8) ? 0 : ((ct < 16) ? 1 : 2);
    const int nc = (ct & 7) * 128;
    const ushort_t* Bh = g_whi + (size_t)mat * 1048576u + (size_t)nc * 1024;
    const ushort_t* Bl = g_wlo + (size_t)mat * 1048576u + (size_t)nc * 1024;

    float* C; size_t ldc; int ccol;
    if (ct < 8)       { C = g_q;  ldc = 1024; ccol = nc; }
    else if (ct < 16) { C = g_kv; ldc = 2048; ccol = nc; }
    else              { C = g_kv; ldc = 2048; ccol = 1024 + nc; }

    gemm_tile(Ah, rt * 128, Bh, Bl, C, ldc, ccol, nullptr);
}

__global__ __launch_bounds__(256, 2) void k_gemm_proj(
    const float* __restrict__ bproj, float* __restrict__ out)
{
    const int ct = blockIdx.x;            // 0..7
    const size_t rt = blockIdx.y;
    const int nc = ct * 128;
    const ushort_t* Bh = g_whi + (size_t)3 * 1048576u + (size_t)nc * 1024;
    const ushort_t* Bl = g_wlo + (size_t)3 * 1048576u + (size_t)nc * 1024;
    gemm_tile(g_wvh, rt * 128, Bh, Bl, out, 1024, nc, bproj);
}

// ---------------------------------------------------------------------------
// dots + softmax(16 heads) + attn*v -> wv (fp16, ready for proj GEMM)
// 256 threads = 16 rows x 16 heads
// ---------------------------------------------------------------------------
__global__ __launch_bounds__(256) void k_attn()
{
    const int tid = threadIdx.x;
    const int h = tid & 15;
    const size_t r = (size_t)blockIdx.x * 16 + (tid >> 4);
    const float4* qp = (const float4*)(g_q  + r * 1024 + h * 64);
    const float4* kp = (const float4*)(g_kv + r * 2048 + h * 64);
    const float4* vp = (const float4*)(g_kv + r * 2048 + 1024 + h * 64);

    float acc = 0.f;
#pragma unroll
    for (int j = 0; j < 16; j++) {
        const float4 a = qp[j], b = kp[j];
        acc += a.x * b.x + a.y * b.y + a.z * b.z + a.w * b.w;
    }
    const float d = acc * (1.0f / 64.0f);   // scale^2 (double-scale in reference)

    float m = d;
#pragma unroll
    for (int s = 8; s; s >>= 1) m = fmaxf(m, __shfl_xor_sync(0xffffffffu, m, s, 16));
    const float e = __expf(d - m);
    float ssum = e;
#pragma unroll
    for (int s = 8; s; s >>= 1) ssum += __shfl_xor_sync(0xffffffffu, ssum, s, 16);
    const float attn = e / ssum;

    uint2* wh = (uint2*)(g_wvh + r * 1024 + h * 64);
#pragma unroll
    for (int j = 0; j < 16; j++) {
        const float4 v = vp[j];
        uint2 H;
        H.x = f16x2_rn(v.y * attn, v.x * attn);
        H.y = f16x2_rn(v.w * attn, v.z * attn);
        wh[j] = H;
    }
}

// ---------------------------------------------------------------------------
// Launch. Inputs: x, y, mask(unused), Wq, Wkv, Wproj, bproj
// ---------------------------------------------------------------------------
extern "C" void kernel_launch(void* const* d_in, const int* in_sizes, int n_in,
                              void* d_out, int out_size)
{
    const float* x     = (const float*)d_in[0];
    const float* y     = (const float*)d_in[1];
    const float* Wq    = (const float*)d_in[3];
    const float* Wkv   = (const float*)d_in[4];
    const float* Wproj = (const float*)d_in[5];
    const float* bproj = (const float*)d_in[6];
    float* out = (float*)d_out;

    const int B = in_sizes[0] / 1024;
    const int n4 = B * 1024 / 4;

    ushort_t *xh, *yh;
    cudaGetSymbolAddress((void**)&xh, g_xh);
    cudaGetSymbolAddress((void**)&yh, g_yh);

    cudaFuncSetAttribute(k_gemm_qkv,  cudaFuncAttributeMaxDynamicSharedMemorySize, SMEM_BYTES);
    cudaFuncSetAttribute(k_gemm_proj, cudaFuncAttributeMaxDynamicSharedMemorySize, SMEM_BYTES);

    k_cvt<<<(n4 + 255) / 256, 256>>>((const float4*)x, (uint2*)xh, n4);
    k_cvt<<<(n4 + 255) / 256, 256>>>((const float4*)y, (uint2*)yh, n4);
    k_prep_w<<<dim3(32, 32, 4), dim3(32, 8)>>>(Wq, Wkv, Wproj);

    k_gemm_qkv<<<dim3(24, B / 128), 256, SMEM_BYTES>>>();
    k_attn<<<B / 16, 256>>>();
    k_gemm_proj<<<dim3(8, B / 128), 256, SMEM_BYTES>>>(bproj, out);
}

// round 8
// speedup vs baseline: 5.8090x; 1.5572x over previous
#include <cuda_runtime.h>
#include <cuda_fp16.h>
#include <cstdint>
#include <cstddef>

typedef unsigned short ushort_t;

// ---------------------------------------------------------------------------
// Scratch (static __device__ arrays; allocation-free rule)
// ---------------------------------------------------------------------------
__device__ float    g_q   [(size_t)65536 * 1024];
__device__ float    g_kv  [(size_t)65536 * 2048];
__device__ ushort_t g_xh  [(size_t)65536 * 1024];   // x as fp16
__device__ ushort_t g_yh  [(size_t)65536 * 1024];   // y as fp16
__device__ ushort_t g_wvh [(size_t)65536 * 1024];   // attn*v as fp16
__device__ ushort_t g_wh  [4u * 1024u * 1024u];     // W^T fp16, [mat][n][k]

// ---------------------------------------------------------------------------
// Portable (sm_80-era) PTX helpers — valid on base sm_100 target.
// ---------------------------------------------------------------------------
__device__ __forceinline__ uint32_t smem_to_u32(const void* p) {
    uint32_t a;
    asm("{ .reg .u64 t; cvta.to.shared.u64 t, %1; cvt.u32.u64 %0, t; }" : "=r"(a) : "l"(p));
    return a;
}
__device__ __forceinline__ void cp_async16(uint32_t dst, const void* src) {
    asm volatile("cp.async.cg.shared.global [%0], [%1], 16;" :: "r"(dst), "l"(src));
}
#define CP_COMMIT()     asm volatile("cp.async.commit_group;" ::: "memory")
#define CP_WAIT(n)      asm volatile("cp.async.wait_group %0;" :: "n"(n) : "memory")

__device__ __forceinline__ void ldsm4(uint32_t* r, uint32_t addr) {
    asm volatile("ldmatrix.sync.aligned.m8n8.x4.shared.b16 {%0,%1,%2,%3}, [%4];"
                 : "=r"(r[0]), "=r"(r[1]), "=r"(r[2]), "=r"(r[3]) : "r"(addr));
}
__device__ __forceinline__ void mma16816(float* c, const uint32_t* a, const uint32_t* b) {
    asm volatile("mma.sync.aligned.m16n8k16.row.col.f32.f16.f16.f32 "
                 "{%0,%1,%2,%3}, {%4,%5,%6,%7}, {%8,%9}, {%0,%1,%2,%3};"
                 : "+f"(c[0]), "+f"(c[1]), "+f"(c[2]), "+f"(c[3])
                 : "r"(a[0]), "r"(a[1]), "r"(a[2]), "r"(a[3]), "r"(b[0]), "r"(b[1]));
}
__device__ __forceinline__ uint32_t f16x2_rn(float hi_val, float lo_val) {
    uint32_t r;
    asm("cvt.rn.f16x2.f32 %0, %1, %2;" : "=r"(r) : "f"(hi_val), "f"(lo_val));
    return r;    // low 16 bits = lo_val
}

// smem swizzle: XOR 16B-unit index (bits 4-6) with row%8 (bits 7-9). Rows = 128B.
#define SW128(off) ((off) ^ (((off) >> 3) & 0x70))

// Stage = A(16KB) + B(16KB) = 32KB; 3-stage ring = 96KB -> 2 CTAs/SM (192KB).
static constexpr uint32_t STAGE_BYTES = 32768;
static constexpr int SMEM_BYTES = 3 * 32768;

// ---------------------------------------------------------------------------
// Activation convert: fp32 -> fp16 (round-to-nearest), float4 vectorized.
// ---------------------------------------------------------------------------
__global__ void k_cvt(const float4* __restrict__ in, uint2* __restrict__ out, int n4)
{
    int i = blockIdx.x * 256 + threadIdx.x;
    if (i >= n4) return;
    const float4 v = in[i];
    uint2 H;
    H.x = f16x2_rn(v.y, v.x);
    H.y = f16x2_rn(v.w, v.z);
    out[i] = H;
}

// ---------------------------------------------------------------------------
// Weight prep: Wt[mat][n][k] = fp16(W[k][n]) (transposed)
// ---------------------------------------------------------------------------
__global__ void k_prep_w(const float* __restrict__ Wq, const float* __restrict__ Wkv,
                         const float* __restrict__ Wproj)
{
    __shared__ float t[32][33];
    const int m = blockIdx.z;
    const float* src; int ld; int coff = 0;
    if (m == 0)      { src = Wq;    ld = 1024; }
    else if (m == 1) { src = Wkv;   ld = 2048; }
    else if (m == 2) { src = Wkv;   ld = 2048; coff = 1024; }
    else             { src = Wproj; ld = 1024; }
    const int n0 = blockIdx.x * 32, k0 = blockIdx.y * 32;
    const int tx = threadIdx.x, ty = threadIdx.y;
#pragma unroll
    for (int j = 0; j < 4; j++)
        t[ty + j * 8][tx] = src[(size_t)(k0 + ty + j * 8) * ld + coff + n0 + tx];
    __syncthreads();
    const size_t base = (size_t)m * 1048576u;
#pragma unroll
    for (int j = 0; j < 4; j++) {
        const int n = n0 + ty + j * 8;
        const int k = k0 + tx;
        g_wh[base + (size_t)n * 1024 + k] =
            __half_as_ushort(__float2half_rn(t[tx][ty + j * 8]));
    }
}

// ---------------------------------------------------------------------------
// Stage one K=64 chunk: A[128x64] + B[128x64] fp16 via cp.async.
// ---------------------------------------------------------------------------
__device__ __forceinline__ void stage_chunk(
    uint32_t sbase, int buf, int kk,
    const ushort_t* __restrict__ Ah, const ushort_t* __restrict__ Bh,
    size_t arow0, int tid)
{
    const int r  = tid >> 1;            // 0..127 (row / n index)
    const int ub = (tid & 1) * 4;       // 16B-unit offset 0 or 4
    const uint32_t so = sbase + (uint32_t)buf * STAGE_BYTES;
    const size_t aoff = (arow0 + r) * 1024 + kk + ub * 8;
    const size_t woff = (size_t)r * 1024 + kk + ub * 8;
#pragma unroll
    for (int u = 0; u < 4; u++) {
        const uint32_t dsw = SW128((uint32_t)(r * 128 + (ub + u) * 16));
        cp_async16(so +          dsw, Ah + aoff + u * 8);
        cp_async16(so + 16384u + dsw, Bh + woff + u * 8);
    }
}

// ---------------------------------------------------------------------------
// Core 128x128 GEMM tile: D = A_fp16 @ B_fp16^T, single-pass, 3-stage ring.
// ---------------------------------------------------------------------------
__device__ __forceinline__ void gemm_tile(
    const ushort_t* __restrict__ Ah, size_t arow0,
    const ushort_t* __restrict__ Bh,
    float* __restrict__ C, size_t ldc, int ccol, const float* __restrict__ bias)
{
    extern __shared__ char smem[];
    const uint32_t sbase = smem_to_u32(smem);
    const int tid = threadIdx.x, lane = tid & 31, wid = tid >> 5;
    const int wm = (wid & 1) * 64;        // 2 warp rows x 64
    const int wn = (wid >> 1) * 32;       // 4 warp cols x 32

    float acc[4][4][4];
#pragma unroll
    for (int i = 0; i < 4; i++)
#pragma unroll
        for (int j = 0; j < 4; j++)
#pragma unroll
            for (int k = 0; k < 4; k++) acc[i][j][k] = 0.f;

    stage_chunk(sbase, 0, 0, Ah, Bh, arow0, tid);
    CP_COMMIT();
    stage_chunk(sbase, 1, 64, Ah, Bh, arow0, tid);
    CP_COMMIT();

    int buf = 0;
    for (int c = 0; c < 16; c++) {
        if (c < 14) {
            int nb = buf + 2; if (nb >= 3) nb -= 3;
            stage_chunk(sbase, nb, (c + 2) * 64, Ah, Bh, arow0, tid);
            CP_COMMIT();
            CP_WAIT(2);
        } else if (c == 14) {
            CP_WAIT(1);
        } else {
            CP_WAIT(0);
        }
        __syncthreads();
        const uint32_t so = sbase + (uint32_t)buf * STAGE_BYTES;
#pragma unroll
        for (int s = 0; s < 4; s++) {
            uint32_t a[4][4];
#pragma unroll
            for (int im = 0; im < 4; im++) {
                const uint32_t row = wm + im * 16 + (lane & 15);
                const uint32_t addr = so + SW128(row * 128 + s * 32 + ((lane >> 4) * 16));
                ldsm4(a[im], addr);
            }
            uint32_t b[4][2];
#pragma unroll
            for (int p = 0; p < 2; p++) {
                const uint32_t t4 = lane >> 3;
                const uint32_t n = wn + p * 16 + ((t4 >> 1) << 3) + (lane & 7);
                const uint32_t addr = so + 16384u + SW128(n * 128 + s * 32 + ((t4 & 1) * 16));
                uint32_t r4[4];
                ldsm4(r4, addr);
                b[p * 2 + 0][0] = r4[0]; b[p * 2 + 0][1] = r4[1];
                b[p * 2 + 1][0] = r4[2]; b[p * 2 + 1][1] = r4[3];
            }
#pragma unroll
            for (int im = 0; im < 4; im++)
#pragma unroll
                for (int jn = 0; jn < 4; jn++)
                    mma16816(acc[im][jn], a[im], b[jn]);
        }
        __syncthreads();
        if (++buf == 3) buf = 0;
    }

    // Epilogue: direct fp32 stores
#pragma unroll
    for (int im = 0; im < 4; im++) {
        const size_t m0 = arow0 + wm + im * 16 + (lane >> 2);
#pragma unroll
        for (int jn = 0; jn < 4; jn++) {
            const int col = ccol + wn + jn * 8 + (lane & 3) * 2;
            float2 v0 = make_float2(acc[im][jn][0], acc[im][jn][1]);
            float2 v1 = make_float2(acc[im][jn][2], acc[im][jn][3]);
            if (bias) {
                const float2 bb = *(const float2*)(bias + col);
                v0.x += bb.x; v0.y += bb.y; v1.x += bb.x; v1.y += bb.y;
            }
            *(float2*)(C + m0 * ldc + col) = v0;
            *(float2*)(C + (m0 + 8) * ldc + col) = v1;
        }
    }
}

// ---------------------------------------------------------------------------
// GEMM kernels
// ---------------------------------------------------------------------------
__global__ __launch_bounds__(256, 2) void k_gemm_qkv()
{
    const int ct = blockIdx.x;            // 0-7: q, 8-15: k, 16-23: v
    const size_t rt = blockIdx.y;
    const ushort_t* Ah = (ct < 8) ? g_xh : g_yh;
    const int mat = (ct < 8) ? 0 : ((ct < 16) ? 1 : 2);
    const int nc = (ct & 7) * 128;
    const ushort_t* Bh = g_wh + (size_t)mat * 1048576u + (size_t)nc * 1024;

    float* C; size_t ldc; int ccol;
    if (ct < 8)       { C = g_q;  ldc = 1024; ccol = nc; }
    else if (ct < 16) { C = g_kv; ldc = 2048; ccol = nc; }
    else              { C = g_kv; ldc = 2048; ccol = 1024 + nc; }

    gemm_tile(Ah, rt * 128, Bh, C, ldc, ccol, nullptr);
}

__global__ __launch_bounds__(256, 2) void k_gemm_proj(
    const float* __restrict__ bproj, float* __restrict__ out)
{
    const int ct = blockIdx.x;            // 0..7
    const size_t rt = blockIdx.y;
    const int nc = ct * 128;
    const ushort_t* Bh = g_wh + (size_t)3 * 1048576u + (size_t)nc * 1024;
    gemm_tile(g_wvh, rt * 128, Bh, out, 1024, nc, bproj);
}

// ---------------------------------------------------------------------------
// dots + softmax(16 heads) + attn*v -> wv (fp16, ready for proj GEMM)
// 256 threads = 16 rows x 16 heads
// ---------------------------------------------------------------------------
__global__ __launch_bounds__(256) void k_attn()
{
    const int tid = threadIdx.x;
    const int h = tid & 15;
    const size_t r = (size_t)blockIdx.x * 16 + (tid >> 4);
    const float4* qp = (const float4*)(g_q  + r * 1024 + h * 64);
    const float4* kp = (const float4*)(g_kv + r * 2048 + h * 64);
    const float4* vp = (const float4*)(g_kv + r * 2048 + 1024 + h * 64);

    float acc = 0.f;
#pragma unroll
    for (int j = 0; j < 16; j++) {
        const float4 a = qp[j], b = kp[j];
        acc += a.x * b.x + a.y * b.y + a.z * b.z + a.w * b.w;
    }
    const float d = acc * (1.0f / 64.0f);   // scale^2 (double-scale in reference)

    float m = d;
#pragma unroll
    for (int s = 8; s; s >>= 1) m = fmaxf(m, __shfl_xor_sync(0xffffffffu, m, s, 16));
    const float e = __expf(d - m);
    float ssum = e;
#pragma unroll
    for (int s = 8; s; s >>= 1) ssum += __shfl_xor_sync(0xffffffffu, ssum, s, 16);
    const float attn = e / ssum;

    uint2* wh = (uint2*)(g_wvh + r * 1024 + h * 64);
#pragma unroll
    for (int j = 0; j < 16; j++) {
        const float4 v = vp[j];
        uint2 H;
        H.x = f16x2_rn(v.y * attn, v.x * attn);
        H.y = f16x2_rn(v.w * attn, v.z * attn);
        wh[j] = H;
    }
}

// ---------------------------------------------------------------------------
// Launch. Inputs: x, y, mask(unused), Wq, Wkv, Wproj, bproj
// ---------------------------------------------------------------------------
extern "C" void kernel_launch(void* const* d_in, const int* in_sizes, int n_in,
                              void* d_out, int out_size)
{
    const float* x     = (const float*)d_in[0];
    const float* y     = (const float*)d_in[1];
    const float* Wq    = (const float*)d_in[3];
    const float* Wkv   = (const float*)d_in[4];
    const float* Wproj = (const float*)d_in[5];
    const float* bproj = (const float*)d_in[6];
    float* out = (float*)d_out;

    const int B = in_sizes[0] / 1024;
    const int n4 = B * 1024 / 4;

    ushort_t *xh, *yh;
    cudaGetSymbolAddress((void**)&xh, g_xh);
    cudaGetSymbolAddress((void**)&yh, g_yh);

    cudaFuncSetAttribute(k_gemm_qkv,  cudaFuncAttributeMaxDynamicSharedMemorySize, SMEM_BYTES);
    cudaFuncSetAttribute(k_gemm_proj, cudaFuncAttributeMaxDynamicSharedMemorySize, SMEM_BYTES);

    k_cvt<<<(n4 + 255) / 256, 256>>>((const float4*)x, (uint2*)xh, n4);
    k_cvt<<<(n4 + 255) / 256, 256>>>((const float4*)y, (uint2*)yh, n4);
    k_prep_w<<<dim3(32, 32, 4), dim3(32, 8)>>>(Wq, Wkv, Wproj);

    k_gemm_qkv<<<dim3(24, B / 128), 256, SMEM_BYTES>>>();
    k_attn<<<B / 16, 256>>>();
    k_gemm_proj<<<dim3(8, B / 128), 256, SMEM_BYTES>>>(bproj, out);
}

// round 10
// speedup vs baseline: 6.3064x; 1.0856x over previous
#include <cuda_runtime.h>
#include <cuda_fp16.h>
#include <cstdint>
#include <cstddef>

typedef unsigned short ushort_t;

// ---------------------------------------------------------------------------
// Scratch (static __device__ arrays; allocation-free rule)
// ---------------------------------------------------------------------------
__device__ ushort_t g_qh  [(size_t)65536 * 1024];   // q  fp16
__device__ ushort_t g_kvh [(size_t)65536 * 2048];   // k|v fp16
__device__ ushort_t g_xh  [(size_t)65536 * 1024];   // x as fp16
__device__ ushort_t g_yh  [(size_t)65536 * 1024];   // y as fp16
__device__ ushort_t g_wvh [(size_t)65536 * 1024];   // attn*v as fp16
__device__ ushort_t g_wh  [4u * 1024u * 1024u];     // W^T fp16, [mat][n][k]

// ---------------------------------------------------------------------------
// Portable (sm_80-era) PTX helpers — valid on base sm_100 target.
// ---------------------------------------------------------------------------
__device__ __forceinline__ uint32_t smem_to_u32(const void* p) {
    uint32_t a;
    asm("{ .reg .u64 t; cvta.to.shared.u64 t, %1; cvt.u32.u64 %0, t; }" : "=r"(a) : "l"(p));
    return a;
}
__device__ __forceinline__ void cp_async16(uint32_t dst, const void* src) {
    asm volatile("cp.async.cg.shared.global [%0], [%1], 16;" :: "r"(dst), "l"(src));
}
#define CP_COMMIT()     asm volatile("cp.async.commit_group;" ::: "memory")
#define CP_WAIT(n)      asm volatile("cp.async.wait_group %0;" :: "n"(n) : "memory")

__device__ __forceinline__ void ldsm4(uint32_t* r, uint32_t addr) {
    asm volatile("ldmatrix.sync.aligned.m8n8.x4.shared.b16 {%0,%1,%2,%3}, [%4];"
                 : "=r"(r[0]), "=r"(r[1]), "=r"(r[2]), "=r"(r[3]) : "r"(addr));
}
__device__ __forceinline__ void mma16816(float* c, const uint32_t* a, const uint32_t* b) {
    asm volatile("mma.sync.aligned.m16n8k16.row.col.f32.f16.f16.f32 "
                 "{%0,%1,%2,%3}, {%4,%5,%6,%7}, {%8,%9}, {%0,%1,%2,%3};"
                 : "+f"(c[0]), "+f"(c[1]), "+f"(c[2]), "+f"(c[3])
                 : "r"(a[0]), "r"(a[1]), "r"(a[2]), "r"(a[3]), "r"(b[0]), "r"(b[1]));
}
__device__ __forceinline__ uint32_t f16x2_rn(float hi_val, float lo_val) {
    uint32_t r;
    asm("cvt.rn.f16x2.f32 %0, %1, %2;" : "=r"(r) : "f"(hi_val), "f"(lo_val));
    return r;    // low 16 bits = lo_val
}

// smem swizzle: XOR 16B-unit index (bits 4-6) with row%8 (bits 7-9). Rows = 128B.
// MUST be applied to the FULL byte offset (incl. the k-step term): the XOR does
// not commute with adding s*32 to an already-swizzled address (R9 bug: OOB).
#define SW128(off) ((off) ^ (((off) >> 3) & 0x70))

// Stage = A(16KB) + B(16KB) = 32KB; 3-stage ring = 96KB -> 2 CTAs/SM (192KB).
static constexpr uint32_t STAGE_BYTES = 32768;
static constexpr int SMEM_BYTES = 3 * 32768;

// ---------------------------------------------------------------------------
// Activation convert: fp32 -> fp16, both x and y in one launch (blockIdx.y).
// ---------------------------------------------------------------------------
__global__ void k_cvt2(const float4* __restrict__ x, const float4* __restrict__ y,
                       uint2* __restrict__ xh, uint2* __restrict__ yh, int n4)
{
    int i = blockIdx.x * 256 + threadIdx.x;
    if (i >= n4) return;
    const float4* in = blockIdx.y ? y : x;
    uint2* out = blockIdx.y ? yh : xh;
    const float4 v = in[i];
    uint2 H;
    H.x = f16x2_rn(v.y, v.x);
    H.y = f16x2_rn(v.w, v.z);
    out[i] = H;
}

// ---------------------------------------------------------------------------
// Weight prep: Wt[mat][n][k] = fp16(W[k][n]) (transposed)
// ---------------------------------------------------------------------------
__global__ void k_prep_w(const float* __restrict__ Wq, const float* __restrict__ Wkv,
                         const float* __restrict__ Wproj)
{
    __shared__ float t[32][33];
    const int m = blockIdx.z;
    const float* src; int ld; int coff = 0;
    if (m == 0)      { src = Wq;    ld = 1024; }
    else if (m == 1) { src = Wkv;   ld = 2048; }
    else if (m == 2) { src = Wkv;   ld = 2048; coff = 1024; }
    else             { src = Wproj; ld = 1024; }
    const int n0 = blockIdx.x * 32, k0 = blockIdx.y * 32;
    const int tx = threadIdx.x, ty = threadIdx.y;
#pragma unroll
    for (int j = 0; j < 4; j++)
        t[ty + j * 8][tx] = src[(size_t)(k0 + ty + j * 8) * ld + coff + n0 + tx];
    __syncthreads();
    const size_t base = (size_t)m * 1048576u;
#pragma unroll
    for (int j = 0; j < 4; j++) {
        const int n = n0 + ty + j * 8;
        const int k = k0 + tx;
        g_wh[base + (size_t)n * 1024 + k] =
            __half_as_ushort(__float2half_rn(t[tx][ty + j * 8]));
    }
}

// ---------------------------------------------------------------------------
// Stage one K=64 chunk: A[128x64] + B[128x64] fp16 via cp.async.
// ---------------------------------------------------------------------------
__device__ __forceinline__ void stage_chunk(
    uint32_t sbase, int buf, int kk,
    const ushort_t* __restrict__ Ah, const ushort_t* __restrict__ Bh,
    size_t arow0, int tid)
{
    const int r  = tid >> 1;            // 0..127 (row / n index)
    const int ub = (tid & 1) * 4;       // 16B-unit offset 0 or 4
    const uint32_t so = sbase + (uint32_t)buf * STAGE_BYTES;
    const size_t aoff = (arow0 + r) * 1024 + kk + ub * 8;
    const size_t woff = (size_t)r * 1024 + kk + ub * 8;
#pragma unroll
    for (int u = 0; u < 4; u++) {
        const uint32_t dsw = SW128((uint32_t)(r * 128 + (ub + u) * 16));
        cp_async16(so +          dsw, Ah + aoff + u * 8);
        cp_async16(so + 16384u + dsw, Bh + woff + u * 8);
    }
}

// ---------------------------------------------------------------------------
// Core 128x128 GEMM tile: D = A_fp16 @ B_fp16^T.
// 3-stage cp.async ring, ONE barrier per chunk, register-pipelined fragments.
// OUT16: write fp16 (q/k/v); else fp32 (+bias) for proj.
// ---------------------------------------------------------------------------
template <bool OUT16>
__device__ __forceinline__ void gemm_tile(
    const ushort_t* __restrict__ Ah, size_t arow0,
    const ushort_t* __restrict__ Bh,
    void* __restrict__ Cout, size_t ldc, int ccol, const float* __restrict__ bias)
{
    extern __shared__ char smem[];
    const uint32_t sbase = smem_to_u32(smem);
    const int tid = threadIdx.x, lane = tid & 31, wid = tid >> 5;
    const int wm = (wid & 1) * 64;        // 2 warp rows x 64
    const int wn = (wid >> 1) * 32;       // 4 warp cols x 32

    float acc[4][4][4];
#pragma unroll
    for (int i = 0; i < 4; i++)
#pragma unroll
        for (int j = 0; j < 4; j++)
#pragma unroll
            for (int k = 0; k < 4; k++) acc[i][j][k] = 0.f;

    // Unswizzled per-fragment row offsets (u0 in {0,1}; u0+2s <= 7: the s-term
    // never carries out of the 3-bit unit field, so SW128(full offset) is exact)
    uint32_t arow_off[4], brow_off[2];
#pragma unroll
    for (int im = 0; im < 4; im++) {
        const uint32_t row = wm + im * 16 + (lane & 15);
        arow_off[im] = row * 128 + ((lane >> 4) * 16);
    }
#pragma unroll
    for (int p = 0; p < 2; p++) {
        const uint32_t t4 = lane >> 3;
        const uint32_t n = wn + p * 16 + ((t4 >> 1) << 3) + (lane & 7);
        brow_off[p] = n * 128 + ((t4 & 1) * 16);
    }

    stage_chunk(sbase, 0, 0, Ah, Bh, arow0, tid);
    CP_COMMIT();
    stage_chunk(sbase, 1, 64, Ah, Bh, arow0, tid);
    CP_COMMIT();

    int buf = 0;
#pragma unroll 1
    for (int c = 0; c < 16; c++) {
        if (c < 15) { CP_WAIT(1); } else { CP_WAIT(0); }
        __syncthreads();
        // Stage c+2 AFTER the barrier: buffer (c+2)%3 was last read at c-1,
        // and every warp passed this barrier only after finishing chunk c-1.
        if (c < 14) {
            int nb = buf + 2; if (nb >= 3) nb -= 3;
            stage_chunk(sbase, nb, (c + 2) * 64, Ah, Bh, arow0, tid);
            CP_COMMIT();
        }
        const uint32_t so = sbase + (uint32_t)buf * STAGE_BYTES;

        uint32_t afr[2][4][4], bfr[2][2][4];
#pragma unroll
        for (int im = 0; im < 4; im++) ldsm4(afr[0][im], so + SW128(arow_off[im]));
#pragma unroll
        for (int p = 0; p < 2; p++)  ldsm4(bfr[0][p], so + 16384u + SW128(brow_off[p]));

#pragma unroll
        for (int s = 0; s < 4; s++) {
            const int cur = s & 1, nxt = cur ^ 1;
            if (s < 3) {
                const uint32_t ko = (uint32_t)(s + 1) * 32;
#pragma unroll
                for (int im = 0; im < 4; im++)
                    ldsm4(afr[nxt][im], so + SW128(arow_off[im] + ko));
#pragma unroll
                for (int p = 0; p < 2; p++)
                    ldsm4(bfr[nxt][p], so + 16384u + SW128(brow_off[p] + ko));
            }
#pragma unroll
            for (int im = 0; im < 4; im++)
#pragma unroll
                for (int jn = 0; jn < 4; jn++)
                    mma16816(acc[im][jn], afr[cur][im], &bfr[cur][jn >> 1][(jn & 1) * 2]);
        }
        if (++buf == 3) buf = 0;
    }

    // Epilogue
#pragma unroll
    for (int im = 0; im < 4; im++) {
        const size_t m0 = arow0 + wm + im * 16 + (lane >> 2);
#pragma unroll
        for (int jn = 0; jn < 4; jn++) {
            const int col = ccol + wn + jn * 8 + (lane & 3) * 2;
            if (OUT16) {
                ushort_t* O = (ushort_t*)Cout;
                *(uint32_t*)(O + m0 * ldc + col)       = f16x2_rn(acc[im][jn][1], acc[im][jn][0]);
                *(uint32_t*)(O + (m0 + 8) * ldc + col) = f16x2_rn(acc[im][jn][3], acc[im][jn][2]);
            } else {
                float* O = (float*)Cout;
                float2 v0 = make_float2(acc[im][jn][0], acc[im][jn][1]);
                float2 v1 = make_float2(acc[im][jn][2], acc[im][jn][3]);
                const float2 bb = *(const float2*)(bias + col);
                v0.x += bb.x; v0.y += bb.y; v1.x += bb.x; v1.y += bb.y;
                *(float2*)(O + m0 * ldc + col) = v0;
                *(float2*)(O + (m0 + 8) * ldc + col) = v1;
            }
        }
    }
}

// ---------------------------------------------------------------------------
// GEMM kernels
// ---------------------------------------------------------------------------
__global__ __launch_bounds__(256, 2) void k_gemm_qkv()
{
    const int ct = blockIdx.x;            // 0-7: q, 8-15: k, 16-23: v
    const size_t rt = blockIdx.y;
    const ushort_t* Ah = (ct < 8) ? g_xh : g_yh;
    const int mat = (ct < 8) ? 0 : ((ct < 16) ? 1 : 2);
    const int nc = (ct & 7) * 128;
    const ushort_t* Bh = g_wh + (size_t)mat * 1048576u + (size_t)nc * 1024;

    ushort_t* C; size_t ldc; int ccol;
    if (ct < 8)       { C = g_qh;  ldc = 1024; ccol = nc; }
    else if (ct < 16) { C = g_kvh; ldc = 2048; ccol = nc; }
    else              { C = g_kvh; ldc = 2048; ccol = 1024 + nc; }

    gemm_tile<true>(Ah, rt * 128, Bh, C, ldc, ccol, nullptr);
}

__global__ __launch_bounds__(256, 2) void k_gemm_proj(
    const float* __restrict__ bproj, float* __restrict__ out)
{
    const int ct = blockIdx.x;            // 0..7
    const size_t rt = blockIdx.y;
    const int nc = ct * 128;
    const ushort_t* Bh = g_wh + (size_t)3 * 1048576u + (size_t)nc * 1024;
    gemm_tile<false>(g_wvh, rt * 128, Bh, out, 1024, nc, bproj);
}

// ---------------------------------------------------------------------------
// dots + softmax(16 heads) + attn*v -> wv (all fp16 traffic)
// 256 threads = 16 rows x 16 heads
// ---------------------------------------------------------------------------
__device__ __forceinline__ float dot8h(uint4 a, uint4 b)
{
    const uint32_t* pa = &a.x;
    const uint32_t* pb = &b.x;
    float s = 0.f;
#pragma unroll
    for (int i = 0; i < 4; i++) {
        const float2 fa = __half22float2(*(const __half2*)&pa[i]);
        const float2 fb = __half22float2(*(const __half2*)&pb[i]);
        s += fa.x * fb.x + fa.y * fb.y;
    }
    return s;
}

__global__ __launch_bounds__(256) void k_attn()
{
    const int tid = threadIdx.x;
    const int h = tid & 15;
    const size_t r = (size_t)blockIdx.x * 16 + (tid >> 4);
    const uint4* qp = (const uint4*)(g_qh  + r * 1024 + h * 64);
    const uint4* kp = (const uint4*)(g_kvh + r * 2048 + h * 64);
    const uint4* vp = (const uint4*)(g_kvh + r * 2048 + 1024 + h * 64);

    float acc = 0.f;
#pragma unroll
    for (int j = 0; j < 8; j++) acc += dot8h(qp[j], kp[j]);
    const float d = acc * (1.0f / 64.0f);   // scale^2 (double-scale in reference)

    float m = d;
#pragma unroll
    for (int s = 8; s; s >>= 1) m = fmaxf(m, __shfl_xor_sync(0xffffffffu, m, s, 16));
    const float e = __expf(d - m);
    float ssum = e;
#pragma unroll
    for (int s = 8; s; s >>= 1) ssum += __shfl_xor_sync(0xffffffffu, ssum, s, 16);
    const float attn = e / ssum;

    uint4* wp = (uint4*)(g_wvh + r * 1024 + h * 64);
#pragma unroll
    for (int j = 0; j < 8; j++) {
        const uint4 v = vp[j];
        const uint32_t* pv = &v.x;
        uint4 o;
        uint32_t* po = &o.x;
#pragma unroll
        for (int i = 0; i < 4; i++) {
            const float2 fv = __half22float2(*(const __half2*)&pv[i]);
            po[i] = f16x2_rn(fv.y * attn, fv.x * attn);
        }
        wp[j] = o;
    }
}

// ---------------------------------------------------------------------------
// Launch. Inputs: x, y, mask(unused), Wq, Wkv, Wproj, bproj
// ---------------------------------------------------------------------------
extern "C" void kernel_launch(void* const* d_in, const int* in_sizes, int n_in,
                              void* d_out, int out_size)
{
    const float* x     = (const float*)d_in[0];
    const float* y     = (const float*)d_in[1];
    const float* Wq    = (const float*)d_in[3];
    const float* Wkv   = (const float*)d_in[4];
    const float* Wproj = (const float*)d_in[5];
    const float* bproj = (const float*)d_in[6];
    float* out = (float*)d_out;

    const int B = in_sizes[0] / 1024;
    const int n4 = B * 1024 / 4;

    ushort_t *xh, *yh;
    cudaGetSymbolAddress((void**)&xh, g_xh);
    cudaGetSymbolAddress((void**)&yh, g_yh);

    cudaFuncSetAttribute(k_gemm_qkv,  cudaFuncAttributeMaxDynamicSharedMemorySize, SMEM_BYTES);
    cudaFuncSetAttribute(k_gemm_proj, cudaFuncAttributeMaxDynamicSharedMemorySize, SMEM_BYTES);

    k_cvt2<<<dim3((n4 + 255) / 256, 2), 256>>>((const float4*)x, (const float4*)y,
                                               (uint2*)xh, (uint2*)yh, n4);
    k_prep_w<<<dim3(32, 32, 4), dim3(32, 8)>>>(Wq, Wkv, Wproj);

    k_gemm_qkv<<<dim3(24, B / 128), 256, SMEM_BYTES>>>();
    k_attn<<<B / 16, 256>>>();
    k_gemm_proj<<<dim3(8, B / 128), 256, SMEM_BYTES>>>(bproj, out);
}

// round 11
// speedup vs baseline: 8.5508x; 1.3559x over previous
#include <cuda_runtime.h>
#include <cuda_fp16.h>
#include <cstdint>
#include <cstddef>

typedef unsigned short ushort_t;

// ---------------------------------------------------------------------------
// Scratch (static __device__ arrays; allocation-free rule)
// ---------------------------------------------------------------------------
__device__ ushort_t g_qh  [(size_t)65536 * 1024];   // q  fp16
__device__ ushort_t g_kvh [(size_t)65536 * 2048];   // k|v fp16
__device__ ushort_t g_xh  [(size_t)65536 * 1024];   // x as fp16
__device__ ushort_t g_yh  [(size_t)65536 * 1024];   // y as fp16
__device__ ushort_t g_wvh [(size_t)65536 * 1024];   // attn*v as fp16
__device__ ushort_t g_wh  [4u * 1024u * 1024u];     // W^T fp16, [mat][n][k]

// ---------------------------------------------------------------------------
// Portable (sm_80-era) PTX helpers — valid on base sm_100 target.
// ---------------------------------------------------------------------------
__device__ __forceinline__ uint32_t smem_to_u32(const void* p) {
    uint32_t a;
    asm("{ .reg .u64 t; cvta.to.shared.u64 t, %1; cvt.u32.u64 %0, t; }" : "=r"(a) : "l"(p));
    return a;
}
__device__ __forceinline__ void cp_async16(uint32_t dst, const void* src) {
    asm volatile("cp.async.cg.shared.global [%0], [%1], 16;" :: "r"(dst), "l"(src));
}
#define CP_COMMIT()     asm volatile("cp.async.commit_group;" ::: "memory")
#define CP_WAIT(n)      asm volatile("cp.async.wait_group %0;" :: "n"(n) : "memory")

__device__ __forceinline__ void ldsm4(uint32_t* r, uint32_t addr) {
    asm volatile("ldmatrix.sync.aligned.m8n8.x4.shared.b16 {%0,%1,%2,%3}, [%4];"
                 : "=r"(r[0]), "=r"(r[1]), "=r"(r[2]), "=r"(r[3]) : "r"(addr));
}
__device__ __forceinline__ void mma16816(float* c, const uint32_t* a, const uint32_t* b) {
    asm volatile("mma.sync.aligned.m16n8k16.row.col.f32.f16.f16.f32 "
                 "{%0,%1,%2,%3}, {%4,%5,%6,%7}, {%8,%9}, {%0,%1,%2,%3};"
                 : "+f"(c[0]), "+f"(c[1]), "+f"(c[2]), "+f"(c[3])
                 : "r"(a[0]), "r"(a[1]), "r"(a[2]), "r"(a[3]), "r"(b[0]), "r"(b[1]));
}
__device__ __forceinline__ uint32_t f16x2_rn(float hi_val, float lo_val) {
    uint32_t r;
    asm("cvt.rn.f16x2.f32 %0, %1, %2;" : "=r"(r) : "f"(hi_val), "f"(lo_val));
    return r;    // low 16 bits = lo_val
}

// smem swizzle: XOR 16B-unit index (bits 4-6) with row%8 (bits 7-9). Rows = 128B.
// MUST be applied to the FULL byte offset (incl. the k-step term).
#define SW128(off) ((off) ^ (((off) >> 3) & 0x70))

// Stage = A(16KB) + B(16KB) = 32KB; 3-stage ring = 96KB -> 2 CTAs/SM (192KB).
static constexpr uint32_t STAGE_BYTES = 32768;
static constexpr int SMEM_BYTES = 3 * 32768;

// ---------------------------------------------------------------------------
// Activation convert: fp32 -> fp16, both x and y in one launch (blockIdx.y).
// ---------------------------------------------------------------------------
__global__ void k_cvt2(const float4* __restrict__ x, const float4* __restrict__ y,
                       uint2* __restrict__ xh, uint2* __restrict__ yh, int n4)
{
    int i = blockIdx.x * 256 + threadIdx.x;
    if (i >= n4) return;
    const float4* in = blockIdx.y ? y : x;
    uint2* out = blockIdx.y ? yh : xh;
    const float4 v = in[i];
    uint2 H;
    H.x = f16x2_rn(v.y, v.x);
    H.y = f16x2_rn(v.w, v.z);
    out[i] = H;
}

// ---------------------------------------------------------------------------
// Weight prep: Wt[mat][n][k] = fp16(W[k][n]) (transposed)
// ---------------------------------------------------------------------------
__global__ void k_prep_w(const float* __restrict__ Wq, const float* __restrict__ Wkv,
                         const float* __restrict__ Wproj)
{
    __shared__ float t[32][33];
    const int m = blockIdx.z;
    const float* src; int ld; int coff = 0;
    if (m == 0)      { src = Wq;    ld = 1024; }
    else if (m == 1) { src = Wkv;   ld = 2048; }
    else if (m == 2) { src = Wkv;   ld = 2048; coff = 1024; }
    else             { src = Wproj; ld = 1024; }
    const int n0 = blockIdx.x * 32, k0 = blockIdx.y * 32;
    const int tx = threadIdx.x, ty = threadIdx.y;
#pragma unroll
    for (int j = 0; j < 4; j++)
        t[ty + j * 8][tx] = src[(size_t)(k0 + ty + j * 8) * ld + coff + n0 + tx];
    __syncthreads();
    const size_t base = (size_t)m * 1048576u;
#pragma unroll
    for (int j = 0; j < 4; j++) {
        const int n = n0 + ty + j * 8;
        const int k = k0 + tx;
        g_wh[base + (size_t)n * 1024 + k] =
            __half_as_ushort(__float2half_rn(t[tx][ty + j * 8]));
    }
}

// ---------------------------------------------------------------------------
// Stage one K=64 chunk: A[128x64] + B[128x64] fp16 via cp.async.
// Coalesced mapping: lane group of 8 covers one FULL 128B gmem line per instr
// (4 lines per warp-instruction = optimal; old mapping touched 16).
// ---------------------------------------------------------------------------
__device__ __forceinline__ void stage_chunk(
    uint32_t sbase, int buf, int kk,
    const ushort_t* __restrict__ Ah, const ushort_t* __restrict__ Bh,
    size_t arow0, int tid)
{
    const int g = tid >> 3;             // 0..31: row group
    const int u = tid & 7;              // 16B unit within the 128B row-slice
    const uint32_t so = sbase + (uint32_t)buf * STAGE_BYTES;
#pragma unroll
    for (int p = 0; p < 4; p++) {
        const int row = p * 32 + g;
        const uint32_t dsw = SW128((uint32_t)(row * 128 + u * 16));
        cp_async16(so +          dsw, Ah + (arow0 + row) * 1024 + kk + u * 8);
        cp_async16(so + 16384u + dsw, Bh + (size_t)row * 1024 + kk + u * 8);
    }
}

// ---------------------------------------------------------------------------
// Core 128x128 GEMM tile: D = A_fp16 @ B_fp16^T.
// 3-stage cp.async ring, ONE barrier per chunk, register-pipelined fragments.
// OUT16: write fp16 (q/k/v); else fp32 (+bias) for proj.
// ---------------------------------------------------------------------------
template <bool OUT16>
__device__ __forceinline__ void gemm_tile(
    const ushort_t* __restrict__ Ah, size_t arow0,
    const ushort_t* __restrict__ Bh,
    void* __restrict__ Cout, size_t ldc, int ccol, const float* __restrict__ bias)
{
    extern __shared__ char smem[];
    const uint32_t sbase = smem_to_u32(smem);
    const int tid = threadIdx.x, lane = tid & 31, wid = tid >> 5;
    const int wm = (wid & 1) * 64;        // 2 warp rows x 64
    const int wn = (wid >> 1) * 32;       // 4 warp cols x 32

    float acc[4][4][4];
#pragma unroll
    for (int i = 0; i < 4; i++)
#pragma unroll
        for (int j = 0; j < 4; j++)
#pragma unroll
            for (int k = 0; k < 4; k++) acc[i][j][k] = 0.f;

    // Unswizzled per-fragment row offsets (u0 in {0,1}; u0+2s <= 7: the s-term
    // never carries out of the 3-bit unit field, so SW128(full offset) is exact)
    uint32_t arow_off[4], brow_off[2];
#pragma unroll
    for (int im = 0; im < 4; im++) {
        const uint32_t row = wm + im * 16 + (lane & 15);
        arow_off[im] = row * 128 + ((lane >> 4) * 16);
    }
#pragma unroll
    for (int p = 0; p < 2; p++) {
        const uint32_t t4 = lane >> 3;
        const uint32_t n = wn + p * 16 + ((t4 >> 1) << 3) + (lane & 7);
        brow_off[p] = n * 128 + ((t4 & 1) * 16);
    }

    stage_chunk(sbase, 0, 0, Ah, Bh, arow0, tid);
    CP_COMMIT();
    stage_chunk(sbase, 1, 64, Ah, Bh, arow0, tid);
    CP_COMMIT();

    int buf = 0;
#pragma unroll 1
    for (int c = 0; c < 16; c++) {
        if (c < 15) { CP_WAIT(1); } else { CP_WAIT(0); }
        __syncthreads();
        // Stage c+2 AFTER the barrier: buffer (c+2)%3 was last read at c-1,
        // and every warp passed this barrier only after finishing chunk c-1.
        if (c < 14) {
            int nb = buf + 2; if (nb >= 3) nb -= 3;
            stage_chunk(sbase, nb, (c + 2) * 64, Ah, Bh, arow0, tid);
            CP_COMMIT();
        }
        const uint32_t so = sbase + (uint32_t)buf * STAGE_BYTES;

        uint32_t afr[2][4][4], bfr[2][2][4];
#pragma unroll
        for (int im = 0; im < 4; im++) ldsm4(afr[0][im], so + SW128(arow_off[im]));
#pragma unroll
        for (int p = 0; p < 2; p++)  ldsm4(bfr[0][p], so + 16384u + SW128(brow_off[p]));

#pragma unroll
        for (int s = 0; s < 4; s++) {
            const int cur = s & 1, nxt = cur ^ 1;
            if (s < 3) {
                const uint32_t ko = (uint32_t)(s + 1) * 32;
#pragma unroll
                for (int im = 0; im < 4; im++)
                    ldsm4(afr[nxt][im], so + SW128(arow_off[im] + ko));
#pragma unroll
                for (int p = 0; p < 2; p++)
                    ldsm4(bfr[nxt][p], so + 16384u + SW128(brow_off[p] + ko));
            }
#pragma unroll
            for (int im = 0; im < 4; im++)
#pragma unroll
                for (int jn = 0; jn < 4; jn++)
                    mma16816(acc[im][jn], afr[cur][im], &bfr[cur][jn >> 1][(jn & 1) * 2]);
        }
        if (++buf == 3) buf = 0;
    }

    // Epilogue
#pragma unroll
    for (int im = 0; im < 4; im++) {
        const size_t m0 = arow0 + wm + im * 16 + (lane >> 2);
#pragma unroll
        for (int jn = 0; jn < 4; jn++) {
            const int col = ccol + wn + jn * 8 + (lane & 3) * 2;
            if (OUT16) {
                ushort_t* O = (ushort_t*)Cout;
                *(uint32_t*)(O + m0 * ldc + col)       = f16x2_rn(acc[im][jn][1], acc[im][jn][0]);
                *(uint32_t*)(O + (m0 + 8) * ldc + col) = f16x2_rn(acc[im][jn][3], acc[im][jn][2]);
            } else {
                float* O = (float*)Cout;
                float2 v0 = make_float2(acc[im][jn][0], acc[im][jn][1]);
                float2 v1 = make_float2(acc[im][jn][2], acc[im][jn][3]);
                const float2 bb = *(const float2*)(bias + col);
                v0.x += bb.x; v0.y += bb.y; v1.x += bb.x; v1.y += bb.y;
                *(float2*)(O + m0 * ldc + col) = v0;
                *(float2*)(O + (m0 + 8) * ldc + col) = v1;
            }
        }
    }
}

// ---------------------------------------------------------------------------
// GEMM kernels
// ---------------------------------------------------------------------------
__global__ __launch_bounds__(256, 2) void k_gemm_qkv()
{
    const int ct = blockIdx.x;            // 0-7: q, 8-15: k, 16-23: v
    const size_t rt = blockIdx.y;
    const ushort_t* Ah = (ct < 8) ? g_xh : g_yh;
    const int mat = (ct < 8) ? 0 : ((ct < 16) ? 1 : 2);
    const int nc = (ct & 7) * 128;
    const ushort_t* Bh = g_wh + (size_t)mat * 1048576u + (size_t)nc * 1024;

    ushort_t* C; size_t ldc; int ccol;
    if (ct < 8)       { C = g_qh;  ldc = 1024; ccol = nc; }
    else if (ct < 16) { C = g_kvh; ldc = 2048; ccol = nc; }
    else              { C = g_kvh; ldc = 2048; ccol = 1024 + nc; }

    gemm_tile<true>(Ah, rt * 128, Bh, C, ldc, ccol, nullptr);
}

__global__ __launch_bounds__(256, 2) void k_gemm_proj(
    const float* __restrict__ bproj, float* __restrict__ out)
{
    const int ct = blockIdx.x;            // 0..7
    const size_t rt = blockIdx.y;
    const int nc = ct * 128;
    const ushort_t* Bh = g_wh + (size_t)3 * 1048576u + (size_t)nc * 1024;
    gemm_tile<false>(g_wvh, rt * 128, Bh, out, 1024, nc, bproj);
}

// ---------------------------------------------------------------------------
// dots + softmax(16 heads) + attn*v -> wv. ONE WARP PER ROW: every load/store
// is 512B contiguous per warp-instruction (4 lines, optimal wavefronts).
// Lane group g = lane>>3 owns heads {4i + g}, i = block index 0..3.
// ---------------------------------------------------------------------------
__device__ __forceinline__ float dot8h(uint4 a, uint4 b)
{
    const uint32_t* pa = &a.x;
    const uint32_t* pb = &b.x;
    float s = 0.f;
#pragma unroll
    for (int i = 0; i < 4; i++) {
        const float2 fa = __half22float2(*(const __half2*)&pa[i]);
        const float2 fb = __half22float2(*(const __half2*)&pb[i]);
        s += fa.x * fb.x + fa.y * fb.y;
    }
    return s;
}

__global__ __launch_bounds__(256) void k_attn()
{
    const int lane = threadIdx.x & 31;
    const int w = threadIdx.x >> 5;
    const size_t r = (size_t)blockIdx.x * 8 + w;
    const uint4* qp = (const uint4*)(g_qh  + r * 1024);
    const uint4* kp = (const uint4*)(g_kvh + r * 2048);
    const uint4* vp = (const uint4*)(g_kvh + r * 2048 + 1024);

    // block i covers halves [i*256, (i+1)*256) = heads 4i..4i+3.
    // lane covers halves [lane*8, lane*8+8) of the block -> head 4i + (lane>>3).
    float d[4];
#pragma unroll
    for (int i = 0; i < 4; i++) {
        const float p0 = dot8h(qp[i * 32 + lane], kp[i * 32 + lane]);
        float p = p0;
        p += __shfl_xor_sync(0xffffffffu, p, 1);
        p += __shfl_xor_sync(0xffffffffu, p, 2);
        p += __shfl_xor_sync(0xffffffffu, p, 4);
        d[i] = p * (1.0f / 64.0f);   // scale^2 (double-scale in reference)
    }

    // softmax over 16 heads: 4 local + cross-group (xor 8, 16)
    float m = fmaxf(fmaxf(d[0], d[1]), fmaxf(d[2], d[3]));
    m = fmaxf(m, __shfl_xor_sync(0xffffffffu, m, 8));
    m = fmaxf(m, __shfl_xor_sync(0xffffffffu, m, 16));
    float e[4], S = 0.f;
#pragma unroll
    for (int i = 0; i < 4; i++) { e[i] = __expf(d[i] - m); S += e[i]; }
    S += __shfl_xor_sync(0xffffffffu, S, 8);
    S += __shfl_xor_sync(0xffffffffu, S, 16);
    const float inv = 1.0f / S;

    uint4* wp = (uint4*)(g_wvh + r * 1024);
#pragma unroll
    for (int i = 0; i < 4; i++) {
        const float a = e[i] * inv;
        const uint4 v = vp[i * 32 + lane];
        const uint32_t* pv = &v.x;
        uint4 o;
        uint32_t* po = &o.x;
#pragma unroll
        for (int j = 0; j < 4; j++) {
            const float2 fv = __half22float2(*(const __half2*)&pv[j]);
            po[j] = f16x2_rn(fv.y * a, fv.x * a);
        }
        wp[i * 32 + lane] = o;
    }
}

// ---------------------------------------------------------------------------
// Launch. Inputs: x, y, mask(unused), Wq, Wkv, Wproj, bproj
// ---------------------------------------------------------------------------
extern "C" void kernel_launch(void* const* d_in, const int* in_sizes, int n_in,
                              void* d_out, int out_size)
{
    const float* x     = (const float*)d_in[0];
    const float* y     = (const float*)d_in[1];
    const float* Wq    = (const float*)d_in[3];
    const float* Wkv   = (const float*)d_in[4];
    const float* Wproj = (const float*)d_in[5];
    const float* bproj = (const float*)d_in[6];
    float* out = (float*)d_out;

    const int B = in_sizes[0] / 1024;
    const int n4 = B * 1024 / 4;

    ushort_t *xh, *yh;
    cudaGetSymbolAddress((void**)&xh, g_xh);
    cudaGetSymbolAddress((void**)&yh, g_yh);

    cudaFuncSetAttribute(k_gemm_qkv,  cudaFuncAttributeMaxDynamicSharedMemorySize, SMEM_BYTES);
    cudaFuncSetAttribute(k_gemm_proj, cudaFuncAttributeMaxDynamicSharedMemorySize, SMEM_BYTES);

    k_cvt2<<<dim3((n4 + 255) / 256, 2), 256>>>((const float4*)x, (const float4*)y,
                                               (uint2*)xh, (uint2*)yh, n4);
    k_prep_w<<<dim3(32, 32, 4), dim3(32, 8)>>>(Wq, Wkv, Wproj);

    k_gemm_qkv<<<dim3(24, B / 128), 256, SMEM_BYTES>>>();
    k_attn<<<B / 8, 256>>>();
    k_gemm_proj<<<dim3(8, B / 128), 256, SMEM_BYTES>>>(bproj, out);
}